// round 11
// baseline (speedup 1.0000x reference)
#include <cuda_runtime.h>
#include <cstdint>

// Problem constants (fixed by the reference)
#define VOCAB 32000
#define D_EMB 768
#define SEQ   2048
#define BATCH 16
#define F4    (D_EMB / 4)        // 192 float4 per row

// Geometry: grid = (256, 6). blockIdx.x -> chunk of 8 s-rows,
// blockIdx.y -> one of 6 c-slices (32 float4 = 128 d values).
// 256 threads = 8 s-rows x 32 c-columns; each warp = one s-row,
// storing 512B contiguous per batch iteration.
#define S_PER_BLK 8
#define C_PER_BLK 32              // float4 columns per block
#define D_PER_BLK (C_PER_BLK * 4) // 128
#define THREADS   (S_PER_BLK * C_PER_BLK) // 256

// ---------------------------------------------------------------------------
// Semantics (from the reference's where() inversion):
//   out[b,s,d] = pe[s,d]
//              + (input_ids[b,s]==0     ? W_tok[d,0]+b_tok[d] : 0)
//              + (segment_label[b,s]==0 ? W_seg[d,0]+b_seg[d] : 0)
//
// R10 -> R11 change: 8 s-rows per block (was 4) with half-width d-slices.
// The strided W_tok column gather (isolated 32B sectors, 1 L1 wavefront each)
// now serves 8 rows instead of 4: total prep wavefronts 393K -> 196K,
// removing ~17% of all L1 traffic. Store/pe coalescing unchanged
// (warp = 512B contiguous). Masks: 4 ballot-packed words (8 rows x 16 bits).
// ---------------------------------------------------------------------------
__global__ void __launch_bounds__(THREADS)
bebert_fused_kernel(const int*   __restrict__ input_ids,
                    const int*   __restrict__ segment_label,
                    const float* __restrict__ W_tok,
                    const float* __restrict__ b_tok,
                    const float* __restrict__ W_seg,
                    const float* __restrict__ b_seg,
                    const float* __restrict__ pe,
                    float*       __restrict__ out)
{
    __shared__ __align__(16) float s_tok[D_PER_BLK];
    __shared__ __align__(16) float s_seg[D_PER_BLK];
    // Packed predicate words: word w covers s-rows {2w, 2w+1};
    // bit layout within a word: bit (r_in_pair*16 + b).
    __shared__ unsigned s_tokbits[S_PER_BLK / 2];
    __shared__ unsigned s_segbits[S_PER_BLK / 2];

    const int t      = threadIdx.x;
    const int s0     = blockIdx.x * S_PER_BLK;
    const int cslice = blockIdx.y;            // 0..5
    const int d0     = cslice * D_PER_BLK;    // first d of this slice

    // --- prep: combined vectors for this slice (threads 0..127) ---
    if (t < D_PER_BLK) {
        const int d = d0 + t;
        s_tok[t] = __ldg(W_tok + (size_t)d * VOCAB) + __ldg(b_tok + d);
        s_seg[t] = __ldg(W_seg + (size_t)d * 3)     + __ldg(b_seg + d);
    }

    // --- masks via warp ballot: 4 warps, warp w covers s-rows {2w, 2w+1} ---
    if (t < (S_PER_BLK / 2) * 32) {           // 128 threads
        const int w = t >> 5;                 // ballot word index 0..3
        const int l = t & 31;
        const int r = (w << 1) + (l >> 4);    // local s-row 0..7
        const int b = l & 15;                 // batch index
        const int row = b * SEQ + s0 + r;
        const unsigned tokv = __ballot_sync(0xFFFFFFFFu,
                                            __ldg(input_ids     + row) == 0);
        const unsigned segv = __ballot_sync(0xFFFFFFFFu,
                                            __ldg(segment_label + row) == 0);
        if (l == 0) { s_tokbits[w] = tokv; s_segbits[w] = segv; }
    }
    __syncthreads();

    const int local_s = t >> 5;               // 0..7 (warp id = s-row)
    const int c_local = t & 31;               // 0..31
    const int s       = s0 + local_s;
    const int c       = cslice * C_PER_BLK + c_local;

    const float4 tv = reinterpret_cast<const float4*>(s_tok)[c_local];
    const float4 sv = reinterpret_cast<const float4*>(s_seg)[c_local];
    const float4 p  = reinterpret_cast<const float4*>(pe + (size_t)s * D_EMB)[c];

    const unsigned tokw = s_tokbits[local_s >> 1] >> ((local_s & 1) << 4);
    const unsigned segw = s_segbits[local_s >> 1] >> ((local_s & 1) << 4);

    float4* out4 = reinterpret_cast<float4*>(out) + (size_t)s * F4 + c;

#pragma unroll
    for (int b = 0; b < BATCH; ++b) {
        float4 r = p;
        if ((tokw >> b) & 1u) { r.x += tv.x; r.y += tv.y; r.z += tv.z; r.w += tv.w; }
        if ((segw >> b) & 1u) { r.x += sv.x; r.y += sv.y; r.z += sv.z; r.w += sv.w; }
        out4[(size_t)b * (SEQ * F4)] = r;      // coalesced 512B per warp
    }
}

// ---------------------------------------------------------------------------
// Launch. Input order (metadata): input_ids, segment_label, W_tok, b_tok,
// W_seg, b_seg, pe. ids arrive as int32 (jax x64 disabled). Output fp32.
// ---------------------------------------------------------------------------
extern "C" void kernel_launch(void* const* d_in, const int* in_sizes, int n_in,
                              void* d_out, int out_size) {
    const int*   input_ids     = (const int*)  d_in[0];
    const int*   segment_label = (const int*)  d_in[1];
    const float* W_tok         = (const float*)d_in[2];
    const float* b_tok         = (const float*)d_in[3];
    const float* W_seg         = (const float*)d_in[4];
    const float* b_seg         = (const float*)d_in[5];
    const float* pe            = (const float*)d_in[6];
    float*       out           = (float*)d_out;

    dim3 grid(SEQ / S_PER_BLK, F4 / C_PER_BLK);   // (256, 6)
    bebert_fused_kernel<<<grid, THREADS>>>(
        input_ids, segment_label, W_tok, b_tok, W_seg, b_seg, pe, out);
}

// round 12
// speedup vs baseline: 1.0625x; 1.0625x over previous
#include <cuda_runtime.h>
#include <cstdint>

// Problem constants (fixed by the reference)
#define VOCAB 32000
#define D_EMB 768
#define SEQ   2048
#define BATCH 16
#define F4    (D_EMB / 4)        // 192 float4 per row

// Geometry: grid = (128, 6), 256 threads (8 warps).
// blockIdx.x -> chunk of 16 s-rows, blockIdx.y -> slice of 32 f4 columns.
// Each WARP owns 2 s-rows (rows {2w, 2w+1}); each thread does 2 x 16 = 32
// float4 stores. 768 blocks total ~ 5.2 blocks/SM -> the entire grid is
// resident in ONE wave (previous geometries ran 1.3 waves with a ~30% tail).
#define S_PER_BLK 16
#define C_PER_BLK 32              // float4 columns per block
#define D_PER_BLK (C_PER_BLK * 4) // 128
#define THREADS   256
#define S_PER_WARP 2

// ---------------------------------------------------------------------------
// Semantics (from the reference's where() inversion):
//   out[b,s,d] = pe[s,d]
//              + (input_ids[b,s]==0     ? W_tok[d,0]+b_tok[d] : 0)
//              + (segment_label[b,s]==0 ? W_seg[d,0]+b_seg[d] : 0)
//
// R11 -> R12 changes:
//  * Single-wave geometry: 768 blocks, 32 stores/thread (2 s-rows per warp).
//  * Masks stay in registers: each warp ballots its own 2 rows x 16 batch
//    predicates; no smem mask table, no LDS on the hot path.
//  * __stcs streaming stores (output never re-read; keep L2 for pe/W_tok).
//  * Prep gather amortized over 16 rows (98K total prep wavefronts).
// ---------------------------------------------------------------------------
__global__ void __launch_bounds__(THREADS, 6)
bebert_fused_kernel(const int*   __restrict__ input_ids,
                    const int*   __restrict__ segment_label,
                    const float* __restrict__ W_tok,
                    const float* __restrict__ b_tok,
                    const float* __restrict__ W_seg,
                    const float* __restrict__ b_seg,
                    const float* __restrict__ pe,
                    float*       __restrict__ out)
{
    __shared__ __align__(16) float s_tok[D_PER_BLK];
    __shared__ __align__(16) float s_seg[D_PER_BLK];

    const int t      = threadIdx.x;
    const int w      = t >> 5;                 // warp 0..7 -> s-rows {2w, 2w+1}
    const int l      = t & 31;                 // lane = f4 column within slice
    const int s0     = blockIdx.x * S_PER_BLK;
    const int cslice = blockIdx.y;             // 0..5
    const int d0     = cslice * D_PER_BLK;

    // --- prep: combined vectors for this slice (threads 0..127) ---
    if (t < D_PER_BLK) {
        const int d = d0 + t;
        s_tok[t] = __ldg(W_tok + (size_t)d * VOCAB) + __ldg(b_tok + d);
        s_seg[t] = __ldg(W_seg + (size_t)d * 3)     + __ldg(b_seg + d);
    }

    // --- masks in registers: this warp ballots its own 2 rows x 16 b ---
    // lane l -> local row (l>>4) of the pair, batch b = l & 15.
    // Resulting word: bit (r_in_pair*16 + b).
    unsigned tokw_full, segw_full;
    {
        const int r   = (w << 1) + (l >> 4);   // local s-row 0..15
        const int b   = l & 15;
        const int row = b * SEQ + s0 + r;
        tokw_full = __ballot_sync(0xFFFFFFFFu, __ldg(input_ids     + row) == 0);
        segw_full = __ballot_sync(0xFFFFFFFFu, __ldg(segment_label + row) == 0);
    }
    __syncthreads();

    const int c = cslice * C_PER_BLK + l;      // global f4 column

    const float4 tv = reinterpret_cast<const float4*>(s_tok)[l];
    const float4 sv = reinterpret_cast<const float4*>(s_seg)[l];

#pragma unroll
    for (int sr = 0; sr < S_PER_WARP; ++sr) {
        const int s = s0 + (w << 1) + sr;
        const float4 p =
            reinterpret_cast<const float4*>(pe + (size_t)s * D_EMB)[c];

        const unsigned tokw = tokw_full >> (sr << 4);  // low 16 bits = this row
        const unsigned segw = segw_full >> (sr << 4);

        float4* out4 = reinterpret_cast<float4*>(out) + (size_t)s * F4 + c;

#pragma unroll
        for (int b = 0; b < BATCH; ++b) {
            float4 r = p;
            if ((tokw >> b) & 1u) { r.x += tv.x; r.y += tv.y; r.z += tv.z; r.w += tv.w; }
            if ((segw >> b) & 1u) { r.x += sv.x; r.y += sv.y; r.z += sv.z; r.w += sv.w; }
            __stcs(out4 + (size_t)b * (SEQ * F4), r);  // streaming, 512B/warp
        }
    }
}

// ---------------------------------------------------------------------------
// Launch. Input order (metadata): input_ids, segment_label, W_tok, b_tok,
// W_seg, b_seg, pe. ids arrive as int32 (jax x64 disabled). Output fp32.
// ---------------------------------------------------------------------------
extern "C" void kernel_launch(void* const* d_in, const int* in_sizes, int n_in,
                              void* d_out, int out_size) {
    const int*   input_ids     = (const int*)  d_in[0];
    const int*   segment_label = (const int*)  d_in[1];
    const float* W_tok         = (const float*)d_in[2];
    const float* b_tok         = (const float*)d_in[3];
    const float* W_seg         = (const float*)d_in[4];
    const float* b_seg         = (const float*)d_in[5];
    const float* pe            = (const float*)d_in[6];
    float*       out           = (float*)d_out;

    dim3 grid(SEQ / S_PER_BLK, F4 / C_PER_BLK);   // (128, 6) = 768 blocks
    bebert_fused_kernel<<<grid, THREADS>>>(
        input_ids, segment_label, W_tok, b_tok, W_seg, b_seg, pe, out);
}